// round 4
// baseline (speedup 1.0000x reference)
#include <cuda_runtime.h>
#include <cuda_bf16.h>
#include <cstdint>

// SABR implied vol with BETA=1, R=Q=0 degeneracies:
//   out[e][t][j] = v * B_t(v) * G_j(v)
//   B_t = 1 + t*(c1*v + c2),  c1 = RHO*VOLVOL/4 = -0.0525, c2 = VOLVOL^2*(2-3RHO^2)/24
//   G_j = Phi_j / (Chi_j + 1e-8), Phi_j = 0.3 * L_j / v,  L_j = -ln(m_j)
//   Chi_j = ln( (sqrt(1 + 1.4*Phi + Phi^2) + Phi + 0.7) / 1.7 )
//   j == 2 (m = 1.0): F == K -> G = 1.  price input mathematically unused.
//
// R4: persistent CTAs + double-buffered smem + bulk-TMA drain.
//   - TMA store removes the 600 cyc/block STG.128 issue cost (R2's real wall).
//   - Double buffering + wait_group 1 overlaps tile i+2 compute with tile i
//     drain, fixing R3's occupancy/serialization collapse.

#define BLK 256
#define TILE_FLOATS (BLK * 25)
#define TILE_BYTES  (TILE_FLOATS * 4)   // 25600
#define CTAS_PER_SM 4
#define NUM_SMS     148

__device__ __forceinline__ uint32_t smem_u32(const void* p) {
    uint32_t a;
    asm("{ .reg .u64 t; cvta.to.shared.u64 t, %1; cvt.u32.u64 %0, t; }"
        : "=r"(a) : "l"(p));
    return a;
}

__global__ __launch_bounds__(BLK, CTAS_PER_SM)
void sabr_kernel(const float* __restrict__ vol, float* __restrict__ out,
                 int n, int ntiles)
{
    __shared__ __align__(128) float sm[2][TILE_FLOATS];

    const int tid = threadIdx.x;
    const int G = gridDim.x;

    int it = 0;
    for (int tile = blockIdx.x; tile < ntiles; tile += G, ++it) {
        const long long base = (long long)tile * BLK;
        const int e = (int)base + tid;
        const int buf = it & 1;

        // ---- compute 25 outputs into registers (overlaps prior drains) ----
        float r[25];
        if (e < n) {
            const float v = vol[e];
            const float slope = fmaf(-0.0525f, v, 0.0019875f);

            const float u = __fdividef(0.3f, v);       // VOLVOL / v
            const float L[4] = { 0.35667494f,   // -ln(0.70)
                                 0.16251893f,   // -ln(0.85)
                                -0.13976194f,   // -ln(1.15)
                                -0.26236426f }; // -ln(1.30)
            float g[5];
            g[2] = 1.0f;
            #pragma unroll
            for (int jj = 0; jj < 4; ++jj) {
                const float Phi = u * L[jj];
                const float h   = fmaf(Phi, Phi, fmaf(1.4f, Phi, 1.0f));
                const float q   = sqrtf(h) + Phi + 0.7f;
                const float Chi = __logf(q * 0.5882353f);   // ln(q/1.7)
                const int j = (jj < 2) ? jj : jj + 1;
                g[j] = __fdividef(Phi, Chi + 1e-8f);
            }
            #pragma unroll
            for (int t = 0; t < 5; ++t) {
                const float vb = v * fmaf((float)t, slope, 1.0f);
                #pragma unroll
                for (int j = 0; j < 5; ++j) r[t * 5 + j] = vb * g[j];
            }
        } else {
            #pragma unroll
            for (int k = 0; k < 25; ++k) r[k] = 0.0f;
        }

        // ---- make sure this buffer's previous drain (tile it-2) finished ----
        if (it >= 2) {
            if (tid == 0)
                asm volatile("cp.async.bulk.wait_group 1;" ::: "memory");
            __syncthreads();
        }

        // ---- stage: stride-25 rows, bank-conflict-free ----
        float* row = sm[buf] + tid * 25;
        #pragma unroll
        for (int k = 0; k < 25; ++k) row[k] = r[k];
        __syncthreads();

        // ---- drain ----
        if (base + BLK <= (long long)n) {
            if (tid == 0) {
                asm volatile("fence.proxy.async.shared::cta;" ::: "memory");
                float* gdst = out + base * 25;
                uint32_t saddr = smem_u32(sm[buf]);
                asm volatile(
                    "cp.async.bulk.global.shared::cta.bulk_group [%0], [%1], %2;"
                    :: "l"(gdst), "r"(saddr), "r"((uint32_t)TILE_BYTES)
                    : "memory");
                asm volatile("cp.async.bulk.commit_group;" ::: "memory");
            }
        } else {
            // partial tail tile (not hit for n % BLK == 0): scalar flush
            float* __restrict__ gout = out + base * 25;
            const long long lim = (long long)n * 25 - base * 25;
            #pragma unroll
            for (int k = 0; k < 25; ++k) {
                const int idx = k * BLK + tid;
                if (idx < lim) gout[idx] = sm[buf][idx];
            }
            __syncthreads();
        }
    }

    // smem must stay live until all outstanding bulk stores have read it
    if (tid == 0)
        asm volatile("cp.async.bulk.wait_group 0;" ::: "memory");
    __syncthreads();
}

extern "C" void kernel_launch(void* const* d_in, const int* in_sizes, int n_in,
                              void* d_out, int out_size)
{
    const float* vol = (const float*)d_in[0];   // metadata order: vol, price
    float* out = (float*)d_out;
    const int n = in_sizes[0];                  // 4096*512 = 2,097,152
    const int ntiles = (n + BLK - 1) / BLK;     // 8192
    int grid = NUM_SMS * CTAS_PER_SM;           // 592 persistent CTAs
    if (grid > ntiles) grid = ntiles;
    sabr_kernel<<<grid, BLK>>>(vol, out, n, ntiles);
}

// round 5
// speedup vs baseline: 1.2357x; 1.2357x over previous
#include <cuda_runtime.h>
#include <cuda_bf16.h>

// SABR implied vol with BETA=1, R=Q=0 degeneracies:
//   out[e][t][j] = v * B_t(v) * G_j(v)
//   B_t = 1 + t*(c1*v + c2),  c1 = RHO*VOLVOL/4 = -0.0525, c2 = VOLVOL^2*(2-3RHO^2)/24
//   G_j = Phi_j / (Chi_j + 1e-8), Phi_j = 0.3 * L_j / v,  L_j = -ln(m_j)
//   Chi_j = ln( (sqrt(1 + 1.4*Phi + Phi^2) + Phi + 0.7) / 1.7 )
//   j == 2 (m = 1.0): F == K -> G = 1.  price input mathematically unused.
//
// R5: warp-autonomous transpose. Each warp owns a private 32x25 smem tile;
// __syncwarp replaces the two block-wide __syncthreads of R2. Removes
// block-barrier skew serialization (8192 x 2 BARs), keeps full 64-warp/SM
// occupancy (25.6KB/CTA -> 8 CTAs/SM).

#define BLK 256
#define WARPS (BLK / 32)
#define WTILE 800            // 32 elements * 25 floats per warp

__global__ __launch_bounds__(BLK)
void sabr_kernel(const float* __restrict__ vol, float* __restrict__ out, int n)
{
    __shared__ __align__(16) float sm[WARPS][WTILE];   // 25.6 KB

    const int tid  = threadIdx.x;
    const int lane = tid & 31;
    const int wid  = tid >> 5;

    const long long base = (long long)blockIdx.x * BLK;
    const long long we0  = base + wid * 32;      // warp's first element
    const int e = (int)we0 + lane;

    // ---- compute 25 outputs ----
    float r[25];
    if (e < n) {
        const float v = vol[e];
        const float slope = fmaf(-0.0525f, v, 0.0019875f);

        const float u = __fdividef(0.3f, v);       // VOLVOL / v
        const float L[4] = { 0.35667494f,   // -ln(0.70)
                             0.16251893f,   // -ln(0.85)
                            -0.13976194f,   // -ln(1.15)
                            -0.26236426f }; // -ln(1.30)
        float g[5];
        g[2] = 1.0f;
        #pragma unroll
        for (int jj = 0; jj < 4; ++jj) {
            const float Phi = u * L[jj];
            // 1 - 2*rho*Phi + Phi^2 = 1 + 1.4*Phi + Phi^2  (always > 0)
            const float h   = fmaf(Phi, Phi, fmaf(1.4f, Phi, 1.0f));
            const float q   = sqrtf(h) + Phi + 0.7f;
            const float Chi = __logf(q * 0.5882353f);   // ln(q/1.7)
            const int j = (jj < 2) ? jj : jj + 1;
            g[j] = __fdividef(Phi, Chi + 1e-8f);
        }
        #pragma unroll
        for (int t = 0; t < 5; ++t) {
            const float vb = v * fmaf((float)t, slope, 1.0f);
            #pragma unroll
            for (int j = 0; j < 5; ++j) r[t * 5 + j] = vb * g[j];
        }
    } else {
        #pragma unroll
        for (int k = 0; k < 25; ++k) r[k] = 0.0f;
    }

    // ---- warp-private transpose through smem ----
    float* row = &sm[wid][lane * 25];   // stride 25 (odd): conflict-free STS
    #pragma unroll
    for (int k = 0; k < 25; ++k) row[k] = r[k];
    __syncwarp();

    // ---- coalesced float4 drain: 200 float4 per warp ----
    if (we0 + 32 <= (long long)n) {
        const float4* __restrict__ s4 = (const float4*)sm[wid];
        float4* __restrict__ g4 = (float4*)(out + we0 * 25);
        #pragma unroll
        for (int k = 0; k < 6; ++k)
            __stcs(&g4[k * 32 + lane], s4[k * 32 + lane]);
        if (lane < 8)
            __stcs(&g4[6 * 32 + lane], s4[6 * 32 + lane]);
    } else {
        // ragged tail warp (never hit for n % 32 == 0): scalar bounded flush
        float* __restrict__ gout = out + we0 * 25;
        const long long lim = (long long)n * 25 - we0 * 25;
        #pragma unroll
        for (int k = 0; k < 25; ++k) {
            const int idx = k * 32 + lane;
            if (idx < lim) gout[idx] = sm[wid][idx];
        }
    }
}

extern "C" void kernel_launch(void* const* d_in, const int* in_sizes, int n_in,
                              void* d_out, int out_size)
{
    const float* vol = (const float*)d_in[0];   // metadata order: vol, price
    float* out = (float*)d_out;
    const int n = in_sizes[0];                  // 4096*512 = 2,097,152
    const int blocks = (n + BLK - 1) / BLK;
    sabr_kernel<<<blocks, BLK>>>(vol, out, n);
}